// round 4
// baseline (speedup 1.0000x reference)
#include <cuda_runtime.h>
#include <math.h>

#define BB 32
#define PP 196
#define EE 2048
#define AA 512
#define DD 512
#define MMM 512
#define VV 10000
#define LLL 20
#define TTT 19
#define KCC 3072   /* M + E + D */
#define G4 2048    /* 4*D */
#define NBIG 12560 /* V + E + A */

#define OFF_PRED  0
#define OFF_CAPS  (BB*TTT*VV)
#define OFF_ALPHA (OFF_CAPS + BB*LLL)
#define OFF_SORT  (OFF_ALPHA + BB*TTT*PP)

typedef unsigned long long ull;

// -------- scratch --------
__device__ float g_att1[BB*PP*AA];
__device__ float g_wcomb[KCC*G4];         // [W_ih | W_hh] k-pair-interleaved
__device__ float g_wic[EE*1024];          // [W_init_h | W_init_c] k-pair-interleaved
__device__ float g_wbig[DD*NBIG];         // [W_fc | W_fbeta | W_dec_att] k-pair-interleaved
__device__ float g_mean[BB*EE];
__device__ float g_h[BB*DD];
__device__ float g_c[BB*DD];
__device__ float g_alpha[BB*PP];
__device__ float g_x[BB*KCC];
__device__ float g_part[48*BB*G4];        // gates / init partials (<=48 segs)
__device__ float g_part2[8*BB*NBIG];      // combined (preds|gate|att2) partials (8 segs)
__device__ int   g_sortind[BB];
__device__ int   g_declen[BB];
__device__ int   g_caps[BB*LLL];

__device__ __forceinline__ float sigm(float x) { return 1.0f / (1.0f + expf(-x)); }

__device__ __forceinline__ ull ffma2(ull a, ull b, ull c) {
    ull d;
    asm("fma.rn.f32x2 %0, %1, %2, %3;" : "=l"(d) : "l"(a), "l"(b), "l"(c));
    return d;
}
__device__ __forceinline__ float pairsum(ull v) {
    float2 f = *reinterpret_cast<float2*>(&v);
    return f.x + f.y;
}
__device__ __forceinline__ ull dup2(float a) {
    ull r;
    asm("mov.b64 %0, {%1, %1};" : "=l"(r) : "f"(a));
    return r;
}

// -------- setup --------
__global__ void k_setup(const int* __restrict__ lens, const int* __restrict__ caps_in,
                        float* __restrict__ out) {
    __shared__ int s_len[BB];
    __shared__ int s_si[BB];
    int tid = threadIdx.x;
    if (tid < BB) s_len[tid] = lens[tid];
    __syncthreads();
    if (tid < BB) {
        int li = s_len[tid];
        int r = 0;
        for (int j = 0; j < BB; ++j) {
            int lj = s_len[j];
            if (lj > li || (lj == li && j < tid)) r++;
        }
        s_si[r] = tid;
    }
    __syncthreads();
    if (tid < BB) {
        int si = s_si[tid];
        g_sortind[tid] = si;
        g_declen[tid]  = s_len[si] - 1;
        out[OFF_SORT + tid] = (float)si;
    }
    __syncthreads();
    for (int i = tid; i < BB*LLL; i += blockDim.x) {
        int b = i / LLL, w = i % LLL;
        int cv = caps_in[s_si[b]*LLL + w];
        g_caps[i] = cv;
        out[OFF_CAPS + i] = (float)cv;
    }
}

// -------- one-time: pack weight blocks, k-pair-interleaved --------
// element (k, j) stored at base[(k>>1)*2N + j*2 + (k&1)]
__global__ void k_pack(const float* __restrict__ W_ih, const float* __restrict__ W_hh,
                       const float* __restrict__ W_fc, const float* __restrict__ W_fbeta,
                       const float* __restrict__ W_dec,
                       const float* __restrict__ Wih0, const float* __restrict__ Wic0) {
    const long long TA = (long long)KCC * G4;
    const long long TB = (long long)DD * NBIG;
    long long idx = (long long)blockIdx.x * 256 + threadIdx.x;
    if (idx < TA) {
        long long a = idx;
        int kp = (int)(a / (2*G4));
        int rem = (int)(a % (2*G4));
        int j = rem >> 1;
        int k = kp*2 + (rem & 1);
        float v = (k < 2560) ? W_ih[(size_t)j*2560 + k] : W_hh[(size_t)j*512 + (k - 2560)];
        g_wcomb[a] = v;
    } else if (idx < TA + TB) {
        long long b = idx - TA;
        int kp = (int)(b / (2*NBIG));
        int rem = (int)(b % (2*NBIG));
        int j = rem >> 1;
        int k = kp*2 + (rem & 1);
        float v;
        if (j < VV)           v = W_fc[(size_t)k*VV + j];
        else if (j < VV + EE) v = W_fbeta[(size_t)k*EE + (j - VV)];
        else                  v = W_dec[(size_t)k*AA + (j - VV - EE)];
        g_wbig[b] = v;
    } else {
        long long c = idx - TA - TB;
        int kp = (int)(c >> 11);
        int rem = (int)(c & 2047);
        int j = rem >> 1;
        int k = kp*2 + (rem & 1);
        float v = (j < 512) ? Wih0[(size_t)k*512 + j] : Wic0[(size_t)k*512 + (j - 512)];
        g_wic[c] = v;
    }
}

// -------- mean over pixels --------
__global__ void k_mean(const float* __restrict__ enc) {
    int b = blockIdx.y;
    int j = (blockIdx.x * 128 + threadIdx.x) * 4;
    int sb = g_sortind[b];
    const float* base = enc + (size_t)sb * PP * EE + j;
    float4 s = make_float4(0.f, 0.f, 0.f, 0.f);
    #pragma unroll 4
    for (int p = 0; p < PP; ++p) {
        float4 v = *reinterpret_cast<const float4*>(base + (size_t)p * EE);
        s.x += v.x; s.y += v.y; s.z += v.z; s.w += v.w;
    }
    const float inv = 1.0f / 196.0f;
    s.x *= inv; s.y *= inv; s.z *= inv; s.w *= inv;
    *reinterpret_cast<float4*>(&g_mean[b*EE + j]) = s;
}

// -------- skinny split-K GEMM: 64-k segments, FFMA2, depth-2 prefetch --------
// grid.x = ceil(N/128), grid.y = K/64. 128 thr: bg = tid>>6 (16 rows), cols j0, j0+64.
__global__ __launch_bounds__(128, 8)
void skinny64(const float* __restrict__ X, int ldx,
              const float* __restrict__ Wp, int N2 /* = 2N */,
              float* __restrict__ part, int npad, int N) {
    __shared__ __align__(16) float Xs[32][64];
    int tid = threadIdx.x;
    int cg = tid & 63, bg = tid >> 6;
    int j0 = blockIdx.x * 128 + cg;
    int j1 = j0 + 64;
    int kb = blockIdx.y * 64;
    #pragma unroll
    for (int i = 0; i < 4; ++i) {
        int f = i * 128 + tid;
        int r = f >> 4, c4 = (f & 15) << 2;
        *reinterpret_cast<float4*>(&Xs[r][c4]) =
            *reinterpret_cast<const float4*>(X + (size_t)r * ldx + kb + c4);
    }
    __syncthreads();
    bool v0 = (j0 < N), v1 = (j1 < N);
    int b0 = bg * 16;
    const float* w0p = Wp + (size_t)(kb >> 1) * N2 + j0 * 2;
    const float* w1p = Wp + (size_t)(kb >> 1) * N2 + j1 * 2;

    ull acc0[16], acc1[16];
    #pragma unroll
    for (int i = 0; i < 16; ++i) { acc0[i] = 0ull; acc1[i] = 0ull; }

    // 16 groups of 4k (2 kpairs); prefetch 2 ahead, 3 rotating buffers
    ull wq[3][4];
    #pragma unroll
    for (int g = 0; g < 2; ++g) {
        size_t o = (size_t)(g * 2) * N2;
        wq[g][0] = v0 ? *reinterpret_cast<const ull*>(w0p + o)      : 0ull;
        wq[g][1] = v0 ? *reinterpret_cast<const ull*>(w0p + o + N2) : 0ull;
        wq[g][2] = v1 ? *reinterpret_cast<const ull*>(w1p + o)      : 0ull;
        wq[g][3] = v1 ? *reinterpret_cast<const ull*>(w1p + o + N2) : 0ull;
    }
    #pragma unroll
    for (int g = 0; g < 16; ++g) {
        int cur = g % 3;
        if (g + 2 < 16) {
            int nxt = (g + 2) % 3;
            size_t o = (size_t)((g + 2) * 2) * N2;
            wq[nxt][0] = v0 ? *reinterpret_cast<const ull*>(w0p + o)      : 0ull;
            wq[nxt][1] = v0 ? *reinterpret_cast<const ull*>(w0p + o + N2) : 0ull;
            wq[nxt][2] = v1 ? *reinterpret_cast<const ull*>(w1p + o)      : 0ull;
            wq[nxt][3] = v1 ? *reinterpret_cast<const ull*>(w1p + o + N2) : 0ull;
        }
        int kk = g * 4;
        #pragma unroll
        for (int i = 0; i < 16; ++i) {
            ulonglong2 xv = *reinterpret_cast<const ulonglong2*>(&Xs[b0 + i][kk]);
            acc0[i] = ffma2(xv.x, wq[cur][0], acc0[i]);
            acc0[i] = ffma2(xv.y, wq[cur][1], acc0[i]);
            acc1[i] = ffma2(xv.x, wq[cur][2], acc1[i]);
            acc1[i] = ffma2(xv.y, wq[cur][3], acc1[i]);
        }
    }
    float* pp = part + ((size_t)blockIdx.y * 32 + b0) * npad;
    #pragma unroll
    for (int i = 0; i < 16; ++i) {
        if (v0) pp[(size_t)i * npad + j0] = pairsum(acc0[i]);
        if (v1) pp[(size_t)i * npad + j1] = pairsum(acc1[i]);
    }
}

// -------- init epilogue: h0/c0 from 32 partials ------------------------------
__global__ void k_init_fin(const float* __restrict__ b_init_h, const float* __restrict__ b_init_c) {
    int idx = blockIdx.x * blockDim.x + threadIdx.x;  // < 16384
    int b = idx >> 9, d = idx & 511;
    float h = b_init_h[d], c = b_init_c[d];
    #pragma unroll
    for (int s = 0; s < 32; ++s) {
        h += g_part[(s*32 + b)*1024 + d];
        c += g_part[(s*32 + b)*1024 + 512 + d];
    }
    g_h[idx] = h;
    g_c[idx] = c;
}

// -------- att1: [6272,2048]x[2048,512] f32x2 SGEMM, 128x64 tiles -------------
__global__ __launch_bounds__(128, 3)
void k_att1(const float* __restrict__ enc, const float* __restrict__ W,
            const float* __restrict__ bias) {
    __shared__ __align__(16) float As[16][128];   // 8 KB
    __shared__ __align__(16) float Bs[16][64];    // 4 KB
    int tid = threadIdx.x;
    int rowBase = blockIdx.x * 128;
    int colBase = blockIdx.y * 64;

    // A: thread tid owns global row rowBase+tid, loads 16 k per tile (4 float4)
    int grow = rowBase + tid;
    const float* asrc = enc + ((size_t)g_sortind[grow / PP] * PP + (grow % PP)) * EE;
    // B: k0 = (tid>>4)*2 (2 rows), n = (tid&15)*4
    int bk0 = (tid >> 4) * 2;
    int bn  = (tid & 15) * 4;
    const float* bsrc = W + (size_t)bk0 * AA + colBase + bn;

    int m0 = (tid >> 3) * 8;   // 16 groups of 8 rows
    int n0 = (tid & 7) * 8;    // 8 groups of 8 cols

    ull acc[8][4];             // n-pair accumulators: acc[i][jp] = {out[m0+i][n0+2jp], [n0+2jp+1]}
    #pragma unroll
    for (int i = 0; i < 8; ++i)
        #pragma unroll
        for (int j = 0; j < 4; ++j) acc[i][j] = 0ull;

    float4 pa[4];
    #pragma unroll
    for (int u = 0; u < 4; ++u) pa[u] = *reinterpret_cast<const float4*>(asrc + 4*u);
    float4 pb0 = *reinterpret_cast<const float4*>(bsrc);
    float4 pb1 = *reinterpret_cast<const float4*>(bsrc + AA);

    for (int kb = 0; kb < EE; kb += 16) {
        #pragma unroll
        for (int u = 0; u < 4; ++u) {
            As[4*u + 0][tid] = pa[u].x;
            As[4*u + 1][tid] = pa[u].y;
            As[4*u + 2][tid] = pa[u].z;
            As[4*u + 3][tid] = pa[u].w;
        }
        *reinterpret_cast<float4*>(&Bs[bk0][bn])     = pb0;
        *reinterpret_cast<float4*>(&Bs[bk0 + 1][bn]) = pb1;
        __syncthreads();
        if (kb + 16 < EE) {
            #pragma unroll
            for (int u = 0; u < 4; ++u)
                pa[u] = *reinterpret_cast<const float4*>(asrc + kb + 16 + 4*u);
            pb0 = *reinterpret_cast<const float4*>(bsrc + (size_t)(kb + 16) * AA);
            pb1 = *reinterpret_cast<const float4*>(bsrc + (size_t)(kb + 17) * AA);
        }
        #pragma unroll
        for (int k = 0; k < 16; ++k) {
            float4 a0 = *reinterpret_cast<const float4*>(&As[k][m0]);
            float4 a1 = *reinterpret_cast<const float4*>(&As[k][m0 + 4]);
            ulonglong2 bp0 = *reinterpret_cast<const ulonglong2*>(&Bs[k][n0]);
            ulonglong2 bp1 = *reinterpret_cast<const ulonglong2*>(&Bs[k][n0 + 4]);
            float am[8] = {a0.x, a0.y, a0.z, a0.w, a1.x, a1.y, a1.z, a1.w};
            #pragma unroll
            for (int i = 0; i < 8; ++i) {
                ull ad = dup2(am[i]);
                acc[i][0] = ffma2(ad, bp0.x, acc[i][0]);
                acc[i][1] = ffma2(ad, bp0.y, acc[i][1]);
                acc[i][2] = ffma2(ad, bp1.x, acc[i][2]);
                acc[i][3] = ffma2(ad, bp1.y, acc[i][3]);
            }
        }
        __syncthreads();
    }
    float2 bb[4];
    #pragma unroll
    for (int jp = 0; jp < 4; ++jp)
        bb[jp] = *reinterpret_cast<const float2*>(bias + colBase + n0 + 2*jp);
    #pragma unroll
    for (int i = 0; i < 8; ++i) {
        int row = rowBase + m0 + i;
        #pragma unroll
        for (int jp = 0; jp < 4; ++jp) {
            float2 r = *reinterpret_cast<float2*>(&acc[i][jp]);
            float2 o = make_float2(r.x + bb[jp].x, r.y + bb[jp].y);
            *reinterpret_cast<float2*>(&g_att1[(size_t)row * AA + colBase + n0 + 2*jp]) = o;
        }
    }
}

// -------- per-step attention --------
__global__ void k_attn(const float* __restrict__ b_dec, const float* __restrict__ W_full,
                       const float* __restrict__ b_full, float* __restrict__ out, int t) {
    __shared__ __align__(16) float att2s[AA];
    __shared__ __align__(16) float wfs[AA];
    __shared__ float es[PP];
    __shared__ float red[256];
    int b = blockIdx.x;
    int tid = threadIdx.x;

    #pragma unroll
    for (int cc = 0; cc < 2; ++cc) {
        int c = tid + cc * 256;
        float a2 = b_dec[c];
        #pragma unroll
        for (int s = 0; s < 8; ++s)
            a2 += g_part2[((size_t)s * 32 + b) * NBIG + VV + EE + c];
        att2s[c] = a2;
        wfs[c] = W_full[c];
    }
    __syncthreads();

    int w = tid >> 5, lane = tid & 31;
    float bf = b_full[0];
    for (int p = w; p < PP; p += 8) {
        const float4* row4 = reinterpret_cast<const float4*>(g_att1 + ((size_t)b * PP + p) * AA);
        const float4* a24  = reinterpret_cast<const float4*>(att2s);
        const float4* wf4  = reinterpret_cast<const float4*>(wfs);
        float part = 0.0f;
        #pragma unroll
        for (int i = 0; i < 4; ++i) {
            int a = lane + i * 32;
            float4 v = row4[a];
            float4 t2 = a24[a];
            float4 wf = wf4[a];
            part = fmaf(fmaxf(v.x + t2.x, 0.f), wf.x, part);
            part = fmaf(fmaxf(v.y + t2.y, 0.f), wf.y, part);
            part = fmaf(fmaxf(v.z + t2.z, 0.f), wf.z, part);
            part = fmaf(fmaxf(v.w + t2.w, 0.f), wf.w, part);
        }
        #pragma unroll
        for (int off = 16; off; off >>= 1) part += __shfl_down_sync(0xffffffffu, part, off);
        if (lane == 0) es[p] = part + bf;
    }
    __syncthreads();

    float v = (tid < PP) ? es[tid] : -1e30f;
    red[tid] = v; __syncthreads();
    for (int s = 128; s > 0; s >>= 1) { if (tid < s) red[tid] = fmaxf(red[tid], red[tid+s]); __syncthreads(); }
    float mx = red[0]; __syncthreads();
    float ex = (tid < PP) ? expf(v - mx) : 0.0f;
    red[tid] = ex; __syncthreads();
    for (int s = 128; s > 0; s >>= 1) { if (tid < s) red[tid] += red[tid+s]; __syncthreads(); }
    float inv = 1.0f / red[0];
    if (tid < PP) {
        float alpha = ex * inv;
        g_alpha[b*PP + tid] = alpha;
        float m = (g_declen[b] > t) ? 1.0f : 0.0f;
        out[OFF_ALPHA + ((size_t)b*TTT + t)*PP + tid] = alpha * m;
    }
}

// -------- staging: g_x = [emb_t | gate*awe | h] --------
__global__ void k_stage(const float* __restrict__ enc, const float* __restrict__ emb,
                        const float* __restrict__ b_fbeta, int t) {
    __shared__ float al[PP];
    int b = blockIdx.y;
    int tid = threadIdx.x;
    for (int i = tid; i < PP; i += 128) al[i] = g_alpha[b*PP + i];
    __syncthreads();

    int j = blockIdx.x * 128 + tid;   // < 3072
    float outv;
    if (j < MMM) {
        int cap = g_caps[b*LLL + t];
        outv = emb[(size_t)cap * MMM + j];
    } else if (j < MMM + EE) {
        int jE = j - MMM;
        int sb = g_sortind[b];
        const float* eb = enc + (size_t)sb * PP * EE + jE;
        float awe0 = 0.f, awe1 = 0.f;
        #pragma unroll 8
        for (int p = 0; p < 192; p += 2) {
            awe0 = fmaf(al[p],     eb[(size_t)p * EE],       awe0);
            awe1 = fmaf(al[p + 1], eb[(size_t)(p + 1) * EE], awe1);
        }
        awe0 = fmaf(al[192], eb[(size_t)192 * EE], awe0);
        awe1 = fmaf(al[193], eb[(size_t)193 * EE], awe1);
        awe0 = fmaf(al[194], eb[(size_t)194 * EE], awe0);
        awe1 = fmaf(al[195], eb[(size_t)195 * EE], awe1);
        float awe = awe0 + awe1;
        float ga = b_fbeta[jE];
        #pragma unroll
        for (int s = 0; s < 8; ++s)
            ga += g_part2[((size_t)s * 32 + b) * NBIG + VV + jE];
        outv = awe * sigm(ga);
    } else {
        outv = g_h[b*DD + (j - (MMM + EE))];
    }
    g_x[b*KCC + j] = outv;
}

// -------- LSTM pointwise (48 gate partials) --------
__global__ void k_lstm(const float* __restrict__ b_ih, const float* __restrict__ b_hh, int t) {
    int idx = blockIdx.x * blockDim.x + threadIdx.x;  // < 16384
    int b = idx >> 9, d = idx & 511;
    float s[4];
    #pragma unroll
    for (int g = 0; g < 4; ++g) {
        float acc = b_ih[g*512 + d] + b_hh[g*512 + d];
        #pragma unroll
        for (int seg = 0; seg < 48; ++seg)
            acc += g_part[((size_t)seg * 32 + b) * G4 + g*512 + d];
        s[g] = acc;
    }
    float ig = sigm(s[0]), fg = sigm(s[1]), gg = tanhf(s[2]), og = sigm(s[3]);
    float cn = fg * g_c[idx] + ig * gg;
    float hn = og * tanhf(cn);
    if (g_declen[b] > t) { g_h[idx] = hn; g_c[idx] = cn; }
}

// -------- masked preds epilogue --------
__global__ void k_fin(const float* __restrict__ b_fc, float* __restrict__ out, int t) {
    int j = blockIdx.x * 256 + threadIdx.x;
    int b = blockIdx.y;
    if (j >= VV) return;
    float v = 0.0f;
    if (g_declen[b] > t) {
        v = b_fc[j];
        #pragma unroll
        for (int s = 0; s < 8; ++s)
            v += g_part2[((size_t)s * 32 + b) * NBIG + j];
    }
    out[OFF_PRED + ((size_t)b*TTT + t)*VV + j] = v;
}

// ============================================================================
extern "C" void kernel_launch(void* const* d_in, const int* in_sizes, int n_in,
                              void* d_out, int out_size) {
    const float* enc       = (const float*)d_in[0];
    const int*   caps_in   = (const int*)  d_in[1];
    const int*   lens      = (const int*)  d_in[2];
    const float* W_enc_att = (const float*)d_in[3];
    const float* b_enc_att = (const float*)d_in[4];
    const float* W_dec_att = (const float*)d_in[5];
    const float* b_dec_att = (const float*)d_in[6];
    const float* W_full    = (const float*)d_in[7];
    const float* b_full    = (const float*)d_in[8];
    const float* emb       = (const float*)d_in[9];
    const float* W_ih      = (const float*)d_in[10];
    const float* W_hh      = (const float*)d_in[11];
    const float* b_ih      = (const float*)d_in[12];
    const float* b_hh      = (const float*)d_in[13];
    const float* W_init_h  = (const float*)d_in[14];
    const float* b_init_h  = (const float*)d_in[15];
    const float* W_init_c  = (const float*)d_in[16];
    const float* b_init_c  = (const float*)d_in[17];
    const float* W_fbeta   = (const float*)d_in[18];
    const float* b_fbeta   = (const float*)d_in[19];
    const float* W_fc      = (const float*)d_in[20];
    const float* b_fc      = (const float*)d_in[21];
    float* out = (float*)d_out;

    float* d_mean; cudaGetSymbolAddress((void**)&d_mean, g_mean);
    float* d_wic;  cudaGetSymbolAddress((void**)&d_wic,  g_wic);
    float* d_part; cudaGetSymbolAddress((void**)&d_part, g_part);
    float* d_p2;   cudaGetSymbolAddress((void**)&d_p2,   g_part2);
    float* d_x;    cudaGetSymbolAddress((void**)&d_x,    g_x);
    float* d_wc;   cudaGetSymbolAddress((void**)&d_wc,   g_wcomb);
    float* d_wb;   cudaGetSymbolAddress((void**)&d_wb,   g_wbig);
    float* d_h;    cudaGetSymbolAddress((void**)&d_h,    g_h);

    k_setup<<<1, 32>>>(lens, caps_in, out);
    k_pack<<<57888, 256>>>(W_ih, W_hh, W_fc, W_fbeta, W_dec_att, W_init_h, W_init_c);
    k_mean<<<dim3(4, BB), 128>>>(enc);
    skinny64<<<dim3(8, 32), 128>>>(d_mean, EE, d_wic, 2048, d_part, 1024, 1024);
    k_init_fin<<<64, 256>>>(b_init_h, b_init_c);
    skinny64<<<dim3(99, 8), 128>>>(d_h, DD, d_wb, 2*NBIG, d_p2, NBIG, NBIG);  // profiled slot
    k_att1<<<dim3(49, 8), 128>>>(enc, W_enc_att, b_enc_att);

    for (int t = 0; t < TTT; ++t) {
        k_attn<<<BB, 256>>>(b_dec_att, W_full, b_full, out, t);
        k_stage<<<dim3(24, BB), 128>>>(enc, emb, b_fbeta, t);
        skinny64<<<dim3(16, 48), 128>>>(d_x, KCC, d_wc, 2*G4, d_part, G4, G4);
        k_lstm<<<64, 256>>>(b_ih, b_hh, t);
        skinny64<<<dim3(99, 8), 128>>>(d_h, DD, d_wb, 2*NBIG, d_p2, NBIG, NBIG);
        k_fin<<<dim3(40, BB), 256>>>(b_fc, out, t);
    }
    (void)in_sizes; (void)n_in; (void)out_size;
}

// round 5
// speedup vs baseline: 1.4756x; 1.4756x over previous
#include <cuda_runtime.h>
#include <math.h>

#define BB 32
#define PP 196
#define EE 2048
#define AA 512
#define DD 512
#define MMM 512
#define VV 10000
#define LLL 20
#define TTT 19
#define KCC 3072   /* M + E + D */
#define G4 2048    /* 4*D */
#define NBIG 12560 /* E + A + V  (fbeta | dec_att | fc) */

#define OFF_PRED  0
#define OFF_CAPS  (BB*TTT*VV)
#define OFF_ALPHA (OFF_CAPS + BB*LLL)
#define OFF_SORT  (OFF_ALPHA + BB*TTT*PP)

/* column offsets inside wbig / part2 */
#define COL_GATE 0        /* [0, 2048)      = W_fbeta */
#define COL_ATT2 2048     /* [2048, 2560)   = W_dec_att */
#define COL_FC   2560     /* [2560, 12560)  = W_fc */

typedef unsigned long long ull;

// -------- scratch --------
__device__ float g_att1[BB*PP*AA];
__device__ float g_wcomb[KCC*G4];         // [W_ih | W_hh] k-pair-interleaved
__device__ float g_wic[EE*1024];          // [W_init_h | W_init_c] k-pair-interleaved
__device__ float g_wbig[DD*NBIG];         // [W_fbeta | W_dec_att | W_fc] k-pair-interleaved
__device__ float g_mean[BB*EE];
__device__ float g_h[BB*DD];
__device__ float g_c[BB*DD];
__device__ float g_alpha[BB*PP];
__device__ float g_x[BB*KCC];
__device__ float g_part[24*BB*G4];        // gates (24 segs) / init (16 segs, width 1024)
__device__ float g_part2[8*BB*NBIG];      // small (8 segs, cols<2560) + preds (4 segs, cols>=2560)
__device__ int   g_sortind[BB];
__device__ int   g_declen[BB];
__device__ int   g_caps[BB*LLL];

__device__ __forceinline__ float sigm(float x) { return 1.0f / (1.0f + expf(-x)); }

__device__ __forceinline__ ull ffma2(ull a, ull b, ull c) {
    ull d;
    asm("fma.rn.f32x2 %0, %1, %2, %3;" : "=l"(d) : "l"(a), "l"(b), "l"(c));
    return d;
}
__device__ __forceinline__ float pairsum(ull v) {
    float2 f = *reinterpret_cast<float2*>(&v);
    return f.x + f.y;
}
__device__ __forceinline__ ull dup2(float a) {
    ull r;
    asm("mov.b64 %0, {%1, %1};" : "=l"(r) : "f"(a));
    return r;
}

// ======================= shared skinny-GEMM body =============================
// M=32 rows, 128-col tile at (colOffset + chunk*128), K segment [seg*KSEG, ..).
// 256 threads: bg=tid>>6 (4 groups x 8 rows), cg=tid&63 -> cols j0 and j0+64.
// Wp is k-pair-interleaved with row stride N2 (floats per k-pair row).
template<int KSEG>
__device__ __forceinline__ void gemm_body(
    float* Xs /* smem, 32*KSEG floats */,
    const float* __restrict__ X, int ldx,
    const float* __restrict__ Wp, int N2,
    float* __restrict__ part, int npad, int N,
    int chunk, int seg, int colOffset)
{
    int tid = threadIdx.x;
    int cg = tid & 63, bg = tid >> 6;
    int j0 = colOffset + chunk * 128 + cg;
    int j1 = j0 + 64;
    int kb = seg * KSEG;

    const int PER = (32 * KSEG / 4) / 256;   // float4 loads per thread (4 or 2)
    #pragma unroll
    for (int i = 0; i < PER; ++i) {
        int f = i * 256 + tid;
        int r = f / (KSEG / 4);
        int c4 = (f % (KSEG / 4)) * 4;
        *reinterpret_cast<float4*>(&Xs[r * KSEG + c4]) =
            *reinterpret_cast<const float4*>(X + (size_t)r * ldx + kb + c4);
    }
    __syncthreads();

    bool v0 = (j0 < N), v1 = (j1 < N);
    int b0 = bg * 8;
    const float* w0p = Wp + (size_t)(kb >> 1) * N2 + j0 * 2;
    const float* w1p = Wp + (size_t)(kb >> 1) * N2 + j1 * 2;

    ull acc0[8], acc1[8];
    #pragma unroll
    for (int i = 0; i < 8; ++i) { acc0[i] = 0ull; acc1[i] = 0ull; }

    const int NG = KSEG / 4;   // groups of 4k (2 kpairs)
    ull wq[3][4];
    #pragma unroll
    for (int g = 0; g < 2; ++g) {
        size_t o = (size_t)(g * 2) * N2;
        wq[g][0] = v0 ? *reinterpret_cast<const ull*>(w0p + o)      : 0ull;
        wq[g][1] = v0 ? *reinterpret_cast<const ull*>(w0p + o + N2) : 0ull;
        wq[g][2] = v1 ? *reinterpret_cast<const ull*>(w1p + o)      : 0ull;
        wq[g][3] = v1 ? *reinterpret_cast<const ull*>(w1p + o + N2) : 0ull;
    }
    #pragma unroll
    for (int g = 0; g < NG; ++g) {
        int cur = g % 3;
        if (g + 2 < NG) {
            int nxt = (g + 2) % 3;
            size_t o = (size_t)((g + 2) * 2) * N2;
            wq[nxt][0] = v0 ? *reinterpret_cast<const ull*>(w0p + o)      : 0ull;
            wq[nxt][1] = v0 ? *reinterpret_cast<const ull*>(w0p + o + N2) : 0ull;
            wq[nxt][2] = v1 ? *reinterpret_cast<const ull*>(w1p + o)      : 0ull;
            wq[nxt][3] = v1 ? *reinterpret_cast<const ull*>(w1p + o + N2) : 0ull;
        }
        int kk = g * 4;
        #pragma unroll
        for (int i = 0; i < 8; ++i) {
            ulonglong2 xv = *reinterpret_cast<const ulonglong2*>(&Xs[(b0 + i) * KSEG + kk]);
            acc0[i] = ffma2(xv.x, wq[cur][0], acc0[i]);
            acc0[i] = ffma2(xv.y, wq[cur][1], acc0[i]);
            acc1[i] = ffma2(xv.x, wq[cur][2], acc1[i]);
            acc1[i] = ffma2(xv.y, wq[cur][3], acc1[i]);
        }
    }
    float* pp = part + ((size_t)seg * 32 + b0) * npad;
    #pragma unroll
    for (int i = 0; i < 8; ++i) {
        if (v0) pp[(size_t)i * npad + j0] = pairsum(acc0[i]);
        if (v1) pp[(size_t)i * npad + j1] = pairsum(acc1[i]);
    }
}

// -------- setup --------
__global__ void k_setup(const int* __restrict__ lens, const int* __restrict__ caps_in,
                        float* __restrict__ out) {
    __shared__ int s_len[BB];
    __shared__ int s_si[BB];
    int tid = threadIdx.x;
    if (tid < BB) s_len[tid] = lens[tid];
    __syncthreads();
    if (tid < BB) {
        int li = s_len[tid];
        int r = 0;
        for (int j = 0; j < BB; ++j) {
            int lj = s_len[j];
            if (lj > li || (lj == li && j < tid)) r++;
        }
        s_si[r] = tid;
    }
    __syncthreads();
    if (tid < BB) {
        int si = s_si[tid];
        g_sortind[tid] = si;
        g_declen[tid]  = s_len[si] - 1;
        out[OFF_SORT + tid] = (float)si;
    }
    __syncthreads();
    for (int i = tid; i < BB*LLL; i += blockDim.x) {
        int b = i / LLL, w = i % LLL;
        int cv = caps_in[s_si[b]*LLL + w];
        g_caps[i] = cv;
        out[OFF_CAPS + i] = (float)cv;
    }
}

// -------- one-time weight packing (k-pair-interleaved) ----------------------
// element (k, j) stored at base[(k>>1)*2N + j*2 + (k&1)]
__global__ void k_pack(const float* __restrict__ W_ih, const float* __restrict__ W_hh,
                       const float* __restrict__ W_fc, const float* __restrict__ W_fbeta,
                       const float* __restrict__ W_dec,
                       const float* __restrict__ Wih0, const float* __restrict__ Wic0) {
    const long long TA = (long long)KCC * G4;
    const long long TB = (long long)DD * NBIG;
    long long idx = (long long)blockIdx.x * 256 + threadIdx.x;
    if (idx < TA) {
        long long a = idx;
        int kp = (int)(a / (2*G4));
        int rem = (int)(a % (2*G4));
        int j = rem >> 1;
        int k = kp*2 + (rem & 1);
        float v = (k < 2560) ? W_ih[(size_t)j*2560 + k] : W_hh[(size_t)j*512 + (k - 2560)];
        g_wcomb[a] = v;
    } else if (idx < TA + TB) {
        long long b = idx - TA;
        int kp = (int)(b / (2*NBIG));
        int rem = (int)(b % (2*NBIG));
        int j = rem >> 1;
        int k = kp*2 + (rem & 1);
        float v;
        if (j < COL_ATT2)     v = W_fbeta[(size_t)k*EE + j];
        else if (j < COL_FC)  v = W_dec[(size_t)k*AA + (j - COL_ATT2)];
        else                  v = W_fc[(size_t)k*VV + (j - COL_FC)];
        g_wbig[b] = v;
    } else {
        long long c = idx - TA - TB;
        int kp = (int)(c >> 11);
        int rem = (int)(c & 2047);
        int j = rem >> 1;
        int k = kp*2 + (rem & 1);
        float v = (j < 512) ? Wih0[(size_t)k*512 + j] : Wic0[(size_t)k*512 + (j - 512)];
        g_wic[c] = v;
    }
}

// -------- mean over pixels --------
__global__ void k_mean(const float* __restrict__ enc) {
    int b = blockIdx.y;
    int j = (blockIdx.x * 128 + threadIdx.x) * 4;
    int sb = g_sortind[b];
    const float* base = enc + (size_t)sb * PP * EE + j;
    float4 s = make_float4(0.f, 0.f, 0.f, 0.f);
    #pragma unroll 4
    for (int p = 0; p < PP; ++p) {
        float4 v = *reinterpret_cast<const float4*>(base + (size_t)p * EE);
        s.x += v.x; s.y += v.y; s.z += v.z; s.w += v.w;
    }
    const float inv = 1.0f / 196.0f;
    s.x *= inv; s.y *= inv; s.z *= inv; s.w *= inv;
    *reinterpret_cast<float4*>(&g_mean[b*EE + j]) = s;
}

// -------- GEMM kernels built on gemm_body ------------------------------------
__global__ __launch_bounds__(256, 3)
void k_gemm_init() {   // mean @ wic: N=1024, K=2048, 16 segs of 128, 8 chunks
    __shared__ __align__(16) float Xs[32*128];
    gemm_body<128>(Xs, g_mean, EE, g_wic, 2048, g_part, 1024, 1024,
                   blockIdx.x, blockIdx.y, 0);
}

__global__ __launch_bounds__(256, 3)
void k_gemm_small() {  // h @ wbig[:, 0:2560]: N=2560, K=512, 8 segs of 64, 20 chunks
    __shared__ __align__(16) float Xs[32*64];
    gemm_body<64>(Xs, g_h, DD, g_wbig, 2*NBIG, g_part2, NBIG, NBIG,
                  blockIdx.x, blockIdx.y, 0);
}

// gates(t): 384 blocks (16 chunks x 24 segs) | preds(t-1): 316 blocks (79 x 4)
__global__ __launch_bounds__(256, 3)
void k_gemm_gates_preds() {
    __shared__ __align__(16) float Xs[32*128];
    int bid = blockIdx.x;
    if (bid < 384) {
        gemm_body<128>(Xs, g_x, KCC, g_wcomb, 2*G4, g_part, G4, G4,
                       bid & 15, bid >> 4, 0);
    } else {
        int q = bid - 384;
        gemm_body<128>(Xs, g_h, DD, g_wbig, 2*NBIG, g_part2, NBIG, NBIG,
                       q % 79, q / 79, COL_FC);
    }
}

__global__ __launch_bounds__(256, 3)
void k_gemm_preds() {  // tail: preds(18) only
    __shared__ __align__(16) float Xs[32*128];
    int q = blockIdx.x;
    gemm_body<128>(Xs, g_h, DD, g_wbig, 2*NBIG, g_part2, NBIG, NBIG,
                   q % 79, q / 79, COL_FC);
}

// -------- init epilogue: h0/c0 from 16 partials ------------------------------
__global__ void k_init_fin(const float* __restrict__ b_init_h, const float* __restrict__ b_init_c) {
    int idx = blockIdx.x * blockDim.x + threadIdx.x;  // < 16384
    int b = idx >> 9, d = idx & 511;
    float h = b_init_h[d], c = b_init_c[d];
    #pragma unroll
    for (int s = 0; s < 16; ++s) {
        h += g_part[(s*32 + b)*1024 + d];
        c += g_part[(s*32 + b)*1024 + 512 + d];
    }
    g_h[idx] = h;
    g_c[idx] = c;
}

// -------- att1: [6272,2048]x[2048,512] f32x2 SGEMM, 128x64 tiles -------------
__global__ __launch_bounds__(128, 3)
void k_att1(const float* __restrict__ enc, const float* __restrict__ W,
            const float* __restrict__ bias) {
    __shared__ __align__(16) float As[16][128];
    __shared__ __align__(16) float Bs[16][64];
    int tid = threadIdx.x;
    int rowBase = blockIdx.x * 128;
    int colBase = blockIdx.y * 64;

    int grow = rowBase + tid;
    const float* asrc = enc + ((size_t)g_sortind[grow / PP] * PP + (grow % PP)) * EE;
    int bk0 = (tid >> 4) * 2;
    int bn  = (tid & 15) * 4;
    const float* bsrc = W + (size_t)bk0 * AA + colBase + bn;

    int m0 = (tid >> 3) * 8;
    int n0 = (tid & 7) * 8;

    ull acc[8][4];
    #pragma unroll
    for (int i = 0; i < 8; ++i)
        #pragma unroll
        for (int j = 0; j < 4; ++j) acc[i][j] = 0ull;

    float4 pa[4];
    #pragma unroll
    for (int u = 0; u < 4; ++u) pa[u] = *reinterpret_cast<const float4*>(asrc + 4*u);
    float4 pb0 = *reinterpret_cast<const float4*>(bsrc);
    float4 pb1 = *reinterpret_cast<const float4*>(bsrc + AA);

    for (int kb = 0; kb < EE; kb += 16) {
        #pragma unroll
        for (int u = 0; u < 4; ++u) {
            As[4*u + 0][tid] = pa[u].x;
            As[4*u + 1][tid] = pa[u].y;
            As[4*u + 2][tid] = pa[u].z;
            As[4*u + 3][tid] = pa[u].w;
        }
        *reinterpret_cast<float4*>(&Bs[bk0][bn])     = pb0;
        *reinterpret_cast<float4*>(&Bs[bk0 + 1][bn]) = pb1;
        __syncthreads();
        if (kb + 16 < EE) {
            #pragma unroll
            for (int u = 0; u < 4; ++u)
                pa[u] = *reinterpret_cast<const float4*>(asrc + kb + 16 + 4*u);
            pb0 = *reinterpret_cast<const float4*>(bsrc + (size_t)(kb + 16) * AA);
            pb1 = *reinterpret_cast<const float4*>(bsrc + (size_t)(kb + 17) * AA);
        }
        #pragma unroll
        for (int k = 0; k < 16; ++k) {
            float4 a0 = *reinterpret_cast<const float4*>(&As[k][m0]);
            float4 a1 = *reinterpret_cast<const float4*>(&As[k][m0 + 4]);
            ulonglong2 bp0 = *reinterpret_cast<const ulonglong2*>(&Bs[k][n0]);
            ulonglong2 bp1 = *reinterpret_cast<const ulonglong2*>(&Bs[k][n0 + 4]);
            float am[8] = {a0.x, a0.y, a0.z, a0.w, a1.x, a1.y, a1.z, a1.w};
            #pragma unroll
            for (int i = 0; i < 8; ++i) {
                ull ad = dup2(am[i]);
                acc[i][0] = ffma2(ad, bp0.x, acc[i][0]);
                acc[i][1] = ffma2(ad, bp0.y, acc[i][1]);
                acc[i][2] = ffma2(ad, bp1.x, acc[i][2]);
                acc[i][3] = ffma2(ad, bp1.y, acc[i][3]);
            }
        }
        __syncthreads();
    }
    float2 bb[4];
    #pragma unroll
    for (int jp = 0; jp < 4; ++jp)
        bb[jp] = *reinterpret_cast<const float2*>(bias + colBase + n0 + 2*jp);
    #pragma unroll
    for (int i = 0; i < 8; ++i) {
        int row = rowBase + m0 + i;
        #pragma unroll
        for (int jp = 0; jp < 4; ++jp) {
            float2 r = *reinterpret_cast<float2*>(&acc[i][jp]);
            float2 o = make_float2(r.x + bb[jp].x, r.y + bb[jp].y);
            *reinterpret_cast<float2*>(&g_att1[(size_t)row * AA + colBase + n0 + 2*jp]) = o;
        }
    }
}

// -------- per-step attention (att2 from part2 cols [2048,2560)) --------------
__global__ void k_attn(const float* __restrict__ b_dec, const float* __restrict__ W_full,
                       const float* __restrict__ b_full, float* __restrict__ out, int t) {
    __shared__ __align__(16) float att2s[AA];
    __shared__ __align__(16) float wfs[AA];
    __shared__ float es[PP];
    __shared__ float red[256];
    int b = blockIdx.x;
    int tid = threadIdx.x;

    #pragma unroll
    for (int cc = 0; cc < 2; ++cc) {
        int c = tid + cc * 256;
        float a2 = b_dec[c];
        #pragma unroll
        for (int s = 0; s < 8; ++s)
            a2 += g_part2[((size_t)s * 32 + b) * NBIG + COL_ATT2 + c];
        att2s[c] = a2;
        wfs[c] = W_full[c];
    }
    __syncthreads();

    int w = tid >> 5, lane = tid & 31;
    float bf = b_full[0];
    for (int p = w; p < PP; p += 8) {
        const float4* row4 = reinterpret_cast<const float4*>(g_att1 + ((size_t)b * PP + p) * AA);
        const float4* a24  = reinterpret_cast<const float4*>(att2s);
        const float4* wf4  = reinterpret_cast<const float4*>(wfs);
        float part = 0.0f;
        #pragma unroll
        for (int i = 0; i < 4; ++i) {
            int a = lane + i * 32;
            float4 v = row4[a];
            float4 t2 = a24[a];
            float4 wf = wf4[a];
            part = fmaf(fmaxf(v.x + t2.x, 0.f), wf.x, part);
            part = fmaf(fmaxf(v.y + t2.y, 0.f), wf.y, part);
            part = fmaf(fmaxf(v.z + t2.z, 0.f), wf.z, part);
            part = fmaf(fmaxf(v.w + t2.w, 0.f), wf.w, part);
        }
        #pragma unroll
        for (int off = 16; off; off >>= 1) part += __shfl_down_sync(0xffffffffu, part, off);
        if (lane == 0) es[p] = part + bf;
    }
    __syncthreads();

    float v = (tid < PP) ? es[tid] : -1e30f;
    red[tid] = v; __syncthreads();
    for (int s = 128; s > 0; s >>= 1) { if (tid < s) red[tid] = fmaxf(red[tid], red[tid+s]); __syncthreads(); }
    float mx = red[0]; __syncthreads();
    float ex = (tid < PP) ? expf(v - mx) : 0.0f;
    red[tid] = ex; __syncthreads();
    for (int s = 128; s > 0; s >>= 1) { if (tid < s) red[tid] += red[tid+s]; __syncthreads(); }
    float inv = 1.0f / red[0];
    if (tid < PP) {
        float alpha = ex * inv;
        g_alpha[b*PP + tid] = alpha;
        float m = (g_declen[b] > t) ? 1.0f : 0.0f;
        out[OFF_ALPHA + ((size_t)b*TTT + t)*PP + tid] = alpha * m;
    }
}

// -------- staging: g_x = [emb_t | gate*awe | h]; gate from part2 cols [0,2048)
__global__ void k_stage(const float* __restrict__ enc, const float* __restrict__ emb,
                        const float* __restrict__ b_fbeta, int t) {
    __shared__ float al[PP];
    int b = blockIdx.y;
    int tid = threadIdx.x;
    for (int i = tid; i < PP; i += 128) al[i] = g_alpha[b*PP + i];
    __syncthreads();

    int j = blockIdx.x * 128 + tid;   // < 3072
    float outv;
    if (j < MMM) {
        int cap = g_caps[b*LLL + t];
        outv = emb[(size_t)cap * MMM + j];
    } else if (j < MMM + EE) {
        int jE = j - MMM;
        int sb = g_sortind[b];
        const float* eb = enc + (size_t)sb * PP * EE + jE;
        float awe0 = 0.f, awe1 = 0.f;
        #pragma unroll 8
        for (int p = 0; p < 192; p += 2) {
            awe0 = fmaf(al[p],     eb[(size_t)p * EE],       awe0);
            awe1 = fmaf(al[p + 1], eb[(size_t)(p + 1) * EE], awe1);
        }
        awe0 = fmaf(al[192], eb[(size_t)192 * EE], awe0);
        awe1 = fmaf(al[193], eb[(size_t)193 * EE], awe1);
        awe0 = fmaf(al[194], eb[(size_t)194 * EE], awe0);
        awe1 = fmaf(al[195], eb[(size_t)195 * EE], awe1);
        float awe = awe0 + awe1;
        float ga = b_fbeta[jE];
        #pragma unroll
        for (int s = 0; s < 8; ++s)
            ga += g_part2[((size_t)s * 32 + b) * NBIG + COL_GATE + jE];
        outv = awe * sigm(ga);
    } else {
        outv = g_h[b*DD + (j - (MMM + EE))];
    }
    g_x[b*KCC + j] = outv;
}

// -------- fin helper (preds from part2 cols [2560,..), 4 segs) ---------------
__device__ __forceinline__ void fin_body(const float* __restrict__ b_fc,
                                         float* __restrict__ out, int t,
                                         int b, int j) {
    if (j >= VV) return;
    float v = 0.0f;
    if (g_declen[b] > t) {
        v = b_fc[j];
        #pragma unroll
        for (int s = 0; s < 4; ++s)
            v += g_part2[((size_t)s * 32 + b) * NBIG + COL_FC + j];
    }
    out[OFF_PRED + ((size_t)b*TTT + t)*VV + j] = v;
}

// -------- merged: lstm(t) [blocks 0..63] + fin(t-1) [blocks 64..1343] --------
__global__ void k_lstm_fin(const float* __restrict__ b_ih, const float* __restrict__ b_hh,
                           const float* __restrict__ b_fc, float* __restrict__ out, int t) {
    int bid = blockIdx.x;
    int tid = threadIdx.x;
    if (bid < 64) {
        int idx = bid * 256 + tid;   // < 16384
        int b = idx >> 9, d = idx & 511;
        float s[4];
        #pragma unroll
        for (int g = 0; g < 4; ++g) {
            float acc = b_ih[g*512 + d] + b_hh[g*512 + d];
            #pragma unroll
            for (int seg = 0; seg < 24; ++seg)
                acc += g_part[((size_t)seg * 32 + b) * G4 + g*512 + d];
            s[g] = acc;
        }
        float ig = sigm(s[0]), fg = sigm(s[1]), gg = tanhf(s[2]), og = sigm(s[3]);
        float cn = fg * g_c[idx] + ig * gg;
        float hn = og * tanhf(cn);
        if (g_declen[b] > t) { g_h[idx] = hn; g_c[idx] = cn; }
    } else {
        int tprev = t - 1;
        if (tprev < 0) return;
        int q = bid - 64;
        int b = q / 40;
        int j = (q % 40) * 256 + tid;
        fin_body(b_fc, out, tprev, b, j);
    }
}

// -------- tail fin for t = TTT-1 ---------------------------------------------
__global__ void k_fin_tail(const float* __restrict__ b_fc, float* __restrict__ out) {
    int b = blockIdx.y;
    int j = blockIdx.x * 256 + threadIdx.x;
    fin_body(b_fc, out, TTT - 1, b, j);
}

// ============================================================================
extern "C" void kernel_launch(void* const* d_in, const int* in_sizes, int n_in,
                              void* d_out, int out_size) {
    const float* enc       = (const float*)d_in[0];
    const int*   caps_in   = (const int*)  d_in[1];
    const int*   lens      = (const int*)  d_in[2];
    const float* W_enc_att = (const float*)d_in[3];
    const float* b_enc_att = (const float*)d_in[4];
    const float* W_dec_att = (const float*)d_in[5];
    const float* b_dec_att = (const float*)d_in[6];
    const float* W_full    = (const float*)d_in[7];
    const float* b_full    = (const float*)d_in[8];
    const float* emb       = (const float*)d_in[9];
    const float* W_ih      = (const float*)d_in[10];
    const float* W_hh      = (const float*)d_in[11];
    const float* b_ih      = (const float*)d_in[12];
    const float* b_hh      = (const float*)d_in[13];
    const float* W_init_h  = (const float*)d_in[14];
    const float* b_init_h  = (const float*)d_in[15];
    const float* W_init_c  = (const float*)d_in[16];
    const float* b_init_c  = (const float*)d_in[17];
    const float* W_fbeta   = (const float*)d_in[18];
    const float* b_fbeta   = (const float*)d_in[19];
    const float* W_fc      = (const float*)d_in[20];
    const float* b_fc      = (const float*)d_in[21];
    float* out = (float*)d_out;

    k_setup<<<1, 32>>>(lens, caps_in, out);
    k_pack<<<57888, 256>>>(W_ih, W_hh, W_fc, W_fbeta, W_dec_att, W_init_h, W_init_c);
    k_mean<<<dim3(4, BB), 128>>>(enc);
    k_gemm_init<<<dim3(8, 16), 256>>>();
    k_init_fin<<<64, 256>>>(b_init_h, b_init_c);
    k_att1<<<dim3(49, 8), 128>>>(enc, W_enc_att, b_enc_att);
    k_gemm_small<<<dim3(20, 8), 256>>>();     // att2(0)/gate(0) from h0

    for (int t = 0; t < TTT; ++t) {
        k_attn<<<BB, 256>>>(b_dec_att, W_full, b_full, out, t);
        k_stage<<<dim3(24, BB), 128>>>(enc, emb, b_fbeta, t);
        k_gemm_gates_preds<<<700, 256>>>();               // gates(t) + preds(t-1)
        k_lstm_fin<<<1344, 256>>>(b_ih, b_hh, b_fc, out, t);  // lstm(t) + fin(t-1)
        if (t < TTT - 1)
            k_gemm_small<<<dim3(20, 8), 256>>>();         // att2(t+1)/gate(t+1)
    }
    k_gemm_preds<<<316, 256>>>();                          // preds(18)
    k_fin_tail<<<dim3(40, BB), 256>>>(b_fc, out);          // fin(18)
    (void)in_sizes; (void)n_in; (void)out_size;
}

// round 7
// speedup vs baseline: 1.5809x; 1.0714x over previous
#include <cuda_runtime.h>
#include <stdint.h>
#include <math.h>

#define BB 32
#define PP 196
#define EE 2048
#define AA 512
#define DD 512
#define MMM 512
#define VV 10000
#define LLL 20
#define TTT 19
#define KCC 3072   /* M + E + D */
#define G4 2048    /* 4*D */
#define NBIG 12560 /* E + A + V  (fbeta | dec_att | fc) */

#define OFF_PRED  0
#define OFF_CAPS  (BB*TTT*VV)
#define OFF_ALPHA (OFF_CAPS + BB*LLL)
#define OFF_SORT  (OFF_ALPHA + BB*TTT*PP)

#define COL_GATE 0
#define COL_ATT2 2048
#define COL_FC   2560

typedef unsigned long long ull;
typedef unsigned int u32;

// -------- scratch --------
__device__ float g_att1[BB*PP*AA];
__device__ float g_wcomb[KCC*G4 + 2048];   // [W_ih | W_hh] k-pair-interleaved (+pad for cp.async tails)
__device__ float g_wic[EE*1024 + 2048];    // [W_init_h | W_init_c]
__device__ float g_wbig[DD*NBIG + 4096];   // [W_fbeta | W_dec_att | W_fc]
__device__ float g_mean[BB*EE];
__device__ float g_h[BB*DD];
__device__ float g_c[BB*DD];
__device__ float g_alpha[BB*PP];
__device__ float g_x[BB*KCC];
__device__ float g_part[24*BB*G4];
__device__ float g_part2[8*BB*NBIG];
__device__ int   g_sortind[BB];
__device__ int   g_declen[BB];
__device__ int   g_caps[BB*LLL];

__device__ __forceinline__ float sigm(float x) { return 1.0f / (1.0f + expf(-x)); }

__device__ __forceinline__ ull ffma2(ull a, ull b, ull c) {
    ull d;
    asm("fma.rn.f32x2 %0, %1, %2, %3;" : "=l"(d) : "l"(a), "l"(b), "l"(c));
    return d;
}
__device__ __forceinline__ float pairsum(ull v) {
    float2 f = *reinterpret_cast<float2*>(&v);
    return f.x + f.y;
}
__device__ __forceinline__ ull dup2(float a) {
    ull r;
    asm("mov.b64 %0, {%1, %1};" : "=l"(r) : "f"(a));
    return r;
}
__device__ __forceinline__ void cp_async16(u32 smem_addr, const void* gptr) {
    asm volatile("cp.async.cg.shared.global [%0], [%1], 16;" :: "r"(smem_addr), "l"(gptr));
}
__device__ __forceinline__ void cp_commit() {
    asm volatile("cp.async.commit_group;" ::: "memory");
}
template<int N> __device__ __forceinline__ void cp_wait() {
    asm volatile("cp.async.wait_group %0;" :: "n"(N) : "memory");
}

// ======================= cp.async skinny-GEMM body ==========================
// M=32 rows x 128-col tile at (colOffset + chunk*128), K segment seg*KSEG.
// 256 threads: bg=tid>>6 (4 groups x 8 rows), cg=tid&63 -> cols j0, j0+64.
// Wp k-pair-interleaved, row stride N2 floats. W streamed via 3-stage cp.async
// in 16k x 128col (8KB) sub-blocks. Ws must hold 3*2048 floats.
template<int KSEG>
__device__ __forceinline__ void gemm4(
    float* Xs, float* Ws,
    const float* __restrict__ X, int ldx,
    const float* __restrict__ Wp, int N2,
    float* __restrict__ part, int npad, int N,
    int chunk, int seg, int colOffset)
{
    int tid = threadIdx.x;
    int cg = tid & 63, bg = tid >> 6;
    int colbase = colOffset + chunk * 128;
    int kb = seg * KSEG;

    // X tile (plain loads; covered by the first __syncthreads)
    const int PER = (32 * KSEG / 4) / 256;
    #pragma unroll
    for (int i = 0; i < PER; ++i) {
        int f = i * 256 + tid;
        int r = f / (KSEG / 4);
        int c4 = (f % (KSEG / 4)) * 4;
        *reinterpret_cast<float4*>(&Xs[r * KSEG + c4]) =
            *reinterpret_cast<const float4*>(X + (size_t)r * ldx + kb + c4);
    }

    const float* wsrc = Wp + (size_t)(kb >> 1) * N2 + (size_t)colbase * 2;
    u32 wsm = (u32)__cvta_generic_to_shared(Ws);
    const int NSB = KSEG / 16;

    // issue sub-block sb: 8 kpair-rows x 256 floats; 2 x 16B per thread
    auto issue = [&](int sb) {
        if (sb < NSB) {
            const float* src = wsrc + (size_t)sb * 8 * N2;
            u32 dst = wsm + (u32)((sb % 3) * 2048 * 4);
            #pragma unroll
            for (int i = 0; i < 2; ++i) {
                int f = i * 256 + tid;
                int r = f >> 6;
                int c = (f & 63) << 2;
                cp_async16(dst + (u32)(r * 256 + c) * 4, src + (size_t)r * N2 + c);
            }
        }
        cp_commit();
    };
    issue(0); issue(1);
    __syncthreads();

    int j0 = colbase + cg, j1 = j0 + 64;
    bool v0 = (j0 < N), v1 = (j1 < N);
    int b0 = bg * 8;

    ull acc0[8], acc1[8];
    #pragma unroll
    for (int i = 0; i < 8; ++i) { acc0[i] = 0ull; acc1[i] = 0ull; }

    for (int sb = 0; sb < NSB; ++sb) {
        cp_wait<1>();
        __syncthreads();
        const float* W0 = Ws + (sb % 3) * 2048;
        int kk = sb * 16;
        #pragma unroll
        for (int kp2 = 0; kp2 < 4; ++kp2) {
            ull wa0 = *reinterpret_cast<const ull*>(W0 + (kp2*2    ) * 256 + cg * 2);
            ull wa1 = *reinterpret_cast<const ull*>(W0 + (kp2*2 + 1) * 256 + cg * 2);
            ull wb0 = *reinterpret_cast<const ull*>(W0 + (kp2*2    ) * 256 + 128 + cg * 2);
            ull wb1 = *reinterpret_cast<const ull*>(W0 + (kp2*2 + 1) * 256 + 128 + cg * 2);
            #pragma unroll
            for (int i = 0; i < 8; ++i) {
                ulonglong2 xv = *reinterpret_cast<const ulonglong2*>(&Xs[(b0 + i) * KSEG + kk + kp2 * 4]);
                acc0[i] = ffma2(xv.x, wa0, acc0[i]);
                acc0[i] = ffma2(xv.y, wa1, acc0[i]);
                acc1[i] = ffma2(xv.x, wb0, acc1[i]);
                acc1[i] = ffma2(xv.y, wb1, acc1[i]);
            }
        }
        __syncthreads();
        issue(sb + 2);
    }

    float* pp = part + ((size_t)seg * 32 + b0) * npad;
    #pragma unroll
    for (int i = 0; i < 8; ++i) {
        if (v0) pp[(size_t)i * npad + j0] = pairsum(acc0[i]);
        if (v1) pp[(size_t)i * npad + j1] = pairsum(acc1[i]);
    }
}

// -------- setup --------
__global__ void k_setup(const int* __restrict__ lens, const int* __restrict__ caps_in,
                        float* __restrict__ out) {
    __shared__ int s_len[BB];
    __shared__ int s_si[BB];
    int tid = threadIdx.x;
    if (tid < BB) s_len[tid] = lens[tid];
    __syncthreads();
    if (tid < BB) {
        int li = s_len[tid];
        int r = 0;
        for (int j = 0; j < BB; ++j) {
            int lj = s_len[j];
            if (lj > li || (lj == li && j < tid)) r++;
        }
        s_si[r] = tid;
    }
    __syncthreads();
    if (tid < BB) {
        int si = s_si[tid];
        g_sortind[tid] = si;
        g_declen[tid]  = s_len[si] - 1;
        out[OFF_SORT + tid] = (float)si;
    }
    __syncthreads();
    for (int i = tid; i < BB*LLL; i += blockDim.x) {
        int b = i / LLL, w = i % LLL;
        int cv = caps_in[s_si[b]*LLL + w];
        g_caps[i] = cv;
        out[OFF_CAPS + i] = (float)cv;
    }
}

// -------- one-time weight packing (k-pair-interleaved) ----------------------
__global__ void k_pack(const float* __restrict__ W_ih, const float* __restrict__ W_hh,
                       const float* __restrict__ W_fc, const float* __restrict__ W_fbeta,
                       const float* __restrict__ W_dec,
                       const float* __restrict__ Wih0, const float* __restrict__ Wic0) {
    const long long TA = (long long)KCC * G4;
    const long long TB = (long long)DD * NBIG;
    long long idx = (long long)blockIdx.x * 256 + threadIdx.x;
    if (idx < TA) {
        long long a = idx;
        int kp = (int)(a / (2*G4));
        int rem = (int)(a % (2*G4));
        int j = rem >> 1;
        int k = kp*2 + (rem & 1);
        float v = (k < 2560) ? W_ih[(size_t)j*2560 + k] : W_hh[(size_t)j*512 + (k - 2560)];
        g_wcomb[a] = v;
    } else if (idx < TA + TB) {
        long long b = idx - TA;
        int kp = (int)(b / (2*NBIG));
        int rem = (int)(b % (2*NBIG));
        int j = rem >> 1;
        int k = kp*2 + (rem & 1);
        float v;
        if (j < COL_ATT2)     v = W_fbeta[(size_t)k*EE + j];
        else if (j < COL_FC)  v = W_dec[(size_t)k*AA + (j - COL_ATT2)];
        else                  v = W_fc[(size_t)k*VV + (j - COL_FC)];
        g_wbig[b] = v;
    } else {
        long long c = idx - TA - TB;
        int kp = (int)(c >> 11);
        int rem = (int)(c & 2047);
        int j = rem >> 1;
        int k = kp*2 + (rem & 1);
        float v = (j < 512) ? Wih0[(size_t)k*512 + j] : Wic0[(size_t)k*512 + (j - 512)];
        g_wic[c] = v;
    }
}

// -------- mean over pixels --------
__global__ void k_mean(const float* __restrict__ enc) {
    int b = blockIdx.y;
    int j = (blockIdx.x * 128 + threadIdx.x) * 4;
    int sb = g_sortind[b];
    const float* base = enc + (size_t)sb * PP * EE + j;
    float4 s = make_float4(0.f, 0.f, 0.f, 0.f);
    #pragma unroll 4
    for (int p = 0; p < PP; ++p) {
        float4 v = *reinterpret_cast<const float4*>(base + (size_t)p * EE);
        s.x += v.x; s.y += v.y; s.z += v.z; s.w += v.w;
    }
    const float inv = 1.0f / 196.0f;
    s.x *= inv; s.y *= inv; s.z *= inv; s.w *= inv;
    *reinterpret_cast<float4*>(&g_mean[b*EE + j]) = s;
}

// -------- GEMM kernels --------
__global__ __launch_bounds__(256, 3)
void k_gemm_init() {   // mean @ wic: N=1024, K=2048, 16 segs, 8 chunks
    __shared__ __align__(16) float Xs[32*128];
    __shared__ __align__(16) float Ws[3*2048];
    gemm4<128>(Xs, Ws, g_mean, EE, g_wic, 2048, g_part, 1024, 1024,
               blockIdx.x, blockIdx.y, 0);
}

__global__ __launch_bounds__(256, 3)
void k_gemm_small() {  // h @ wbig[:,0:2560]: N=2560, K=512, 8 segs of 64, 20 chunks
    __shared__ __align__(16) float Xs[32*64];
    __shared__ __align__(16) float Ws[3*2048];
    gemm4<64>(Xs, Ws, g_h, DD, g_wbig, 2*NBIG, g_part2, NBIG, NBIG,
              blockIdx.x, blockIdx.y, 0);
}

// gates(t): 384 blocks | preds(t-1): 316 blocks
__global__ __launch_bounds__(256, 3)
void k_gemm_gates_preds() {
    __shared__ __align__(16) float Xs[32*128];
    __shared__ __align__(16) float Ws[3*2048];
    int bid = blockIdx.x;
    if (bid < 384) {
        gemm4<128>(Xs, Ws, g_x, KCC, g_wcomb, 2*G4, g_part, G4, G4,
                   bid & 15, bid >> 4, 0);
    } else {
        int q = bid - 384;
        gemm4<128>(Xs, Ws, g_h, DD, g_wbig, 2*NBIG, g_part2, NBIG, NBIG,
                   q % 79, q / 79, COL_FC);
    }
}

__global__ __launch_bounds__(256, 3)
void k_gemm_preds() {  // tail: preds(18)
    __shared__ __align__(16) float Xs[32*128];
    __shared__ __align__(16) float Ws[3*2048];
    int q = blockIdx.x;
    gemm4<128>(Xs, Ws, g_h, DD, g_wbig, 2*NBIG, g_part2, NBIG, NBIG,
               q % 79, q / 79, COL_FC);
}

// -------- init epilogue --------
__global__ void k_init_fin(const float* __restrict__ b_init_h, const float* __restrict__ b_init_c) {
    int idx = blockIdx.x * blockDim.x + threadIdx.x;
    int b = idx >> 9, d = idx & 511;
    float h = b_init_h[d], c = b_init_c[d];
    #pragma unroll
    for (int s = 0; s < 16; ++s) {
        h += g_part[(s*32 + b)*1024 + d];
        c += g_part[(s*32 + b)*1024 + 512 + d];
    }
    g_h[idx] = h;
    g_c[idx] = c;
}

// -------- att1: [6272,2048]x[2048,512] f32x2 SGEMM, 128x64 tiles -------------
__global__ __launch_bounds__(128, 3)
void k_att1(const float* __restrict__ enc, const float* __restrict__ W,
            const float* __restrict__ bias) {
    __shared__ __align__(16) float As[16][128];
    __shared__ __align__(16) float Bs[16][64];
    int tid = threadIdx.x;
    int rowBase = blockIdx.x * 128;
    int colBase = blockIdx.y * 64;

    int grow = rowBase + tid;
    const float* asrc = enc + ((size_t)g_sortind[grow / PP] * PP + (grow % PP)) * EE;
    int bk0 = (tid >> 4) * 2;
    int bn  = (tid & 15) * 4;
    const float* bsrc = W + (size_t)bk0 * AA + colBase + bn;

    int m0 = (tid >> 3) * 8;
    int n0 = (tid & 7) * 8;

    ull acc[8][4];
    #pragma unroll
    for (int i = 0; i < 8; ++i)
        #pragma unroll
        for (int j = 0; j < 4; ++j) acc[i][j] = 0ull;

    float4 pa[4];
    #pragma unroll
    for (int u = 0; u < 4; ++u) pa[u] = *reinterpret_cast<const float4*>(asrc + 4*u);
    float4 pb0 = *reinterpret_cast<const float4*>(bsrc);
    float4 pb1 = *reinterpret_cast<const float4*>(bsrc + AA);

    for (int kb = 0; kb < EE; kb += 16) {
        #pragma unroll
        for (int u = 0; u < 4; ++u) {
            As[4*u + 0][tid] = pa[u].x;
            As[4*u + 1][tid] = pa[u].y;
            As[4*u + 2][tid] = pa[u].z;
            As[4*u + 3][tid] = pa[u].w;
        }
        *reinterpret_cast<float4*>(&Bs[bk0][bn])     = pb0;
        *reinterpret_cast<float4*>(&Bs[bk0 + 1][bn]) = pb1;
        __syncthreads();
        if (kb + 16 < EE) {
            #pragma unroll
            for (int u = 0; u < 4; ++u)
                pa[u] = *reinterpret_cast<const float4*>(asrc + kb + 16 + 4*u);
            pb0 = *reinterpret_cast<const float4*>(bsrc + (size_t)(kb + 16) * AA);
            pb1 = *reinterpret_cast<const float4*>(bsrc + (size_t)(kb + 17) * AA);
        }
        #pragma unroll
        for (int k = 0; k < 16; ++k) {
            float4 a0 = *reinterpret_cast<const float4*>(&As[k][m0]);
            float4 a1 = *reinterpret_cast<const float4*>(&As[k][m0 + 4]);
            ulonglong2 bp0 = *reinterpret_cast<const ulonglong2*>(&Bs[k][n0]);
            ulonglong2 bp1 = *reinterpret_cast<const ulonglong2*>(&Bs[k][n0 + 4]);
            float am[8] = {a0.x, a0.y, a0.z, a0.w, a1.x, a1.y, a1.z, a1.w};
            #pragma unroll
            for (int i = 0; i < 8; ++i) {
                ull ad = dup2(am[i]);
                acc[i][0] = ffma2(ad, bp0.x, acc[i][0]);
                acc[i][1] = ffma2(ad, bp0.y, acc[i][1]);
                acc[i][2] = ffma2(ad, bp1.x, acc[i][2]);
                acc[i][3] = ffma2(ad, bp1.y, acc[i][3]);
            }
        }
        __syncthreads();
    }
    float2 bb[4];
    #pragma unroll
    for (int jp = 0; jp < 4; ++jp)
        bb[jp] = *reinterpret_cast<const float2*>(bias + colBase + n0 + 2*jp);
    #pragma unroll
    for (int i = 0; i < 8; ++i) {
        int row = rowBase + m0 + i;
        #pragma unroll
        for (int jp = 0; jp < 4; ++jp) {
            float2 r = *reinterpret_cast<float2*>(&acc[i][jp]);
            float2 o = make_float2(r.x + bb[jp].x, r.y + bb[jp].y);
            *reinterpret_cast<float2*>(&g_att1[(size_t)row * AA + colBase + n0 + 2*jp]) = o;
        }
    }
}

// -------- per-step attention --------
__global__ void k_attn(const float* __restrict__ b_dec, const float* __restrict__ W_full,
                       const float* __restrict__ b_full, float* __restrict__ out, int t) {
    __shared__ __align__(16) float att2s[AA];
    __shared__ __align__(16) float wfs[AA];
    __shared__ float es[PP];
    __shared__ float red[256];
    int b = blockIdx.x;
    int tid = threadIdx.x;

    #pragma unroll
    for (int cc = 0; cc < 2; ++cc) {
        int c = tid + cc * 256;
        float a2 = b_dec[c];
        #pragma unroll
        for (int s = 0; s < 8; ++s)
            a2 += g_part2[((size_t)s * 32 + b) * NBIG + COL_ATT2 + c];
        att2s[c] = a2;
        wfs[c] = W_full[c];
    }
    __syncthreads();

    int w = tid >> 5, lane = tid & 31;
    float bf = b_full[0];
    for (int p = w; p < PP; p += 8) {
        const float4* row4 = reinterpret_cast<const float4*>(g_att1 + ((size_t)b * PP + p) * AA);
        const float4* a24  = reinterpret_cast<const float4*>(att2s);
        const float4* wf4  = reinterpret_cast<const float4*>(wfs);
        float part = 0.0f;
        #pragma unroll
        for (int i = 0; i < 4; ++i) {
            int a = lane + i * 32;
            float4 v = row4[a];
            float4 t2 = a24[a];
            float4 wf = wf4[a];
            part = fmaf(fmaxf(v.x + t2.x, 0.f), wf.x, part);
            part = fmaf(fmaxf(v.y + t2.y, 0.f), wf.y, part);
            part = fmaf(fmaxf(v.z + t2.z, 0.f), wf.z, part);
            part = fmaf(fmaxf(v.w + t2.w, 0.f), wf.w, part);
        }
        #pragma unroll
        for (int off = 16; off; off >>= 1) part += __shfl_down_sync(0xffffffffu, part, off);
        if (lane == 0) es[p] = part + bf;
    }
    __syncthreads();

    float v = (tid < PP) ? es[tid] : -1e30f;
    red[tid] = v; __syncthreads();
    for (int s = 128; s > 0; s >>= 1) { if (tid < s) red[tid] = fmaxf(red[tid], red[tid+s]); __syncthreads(); }
    float mx = red[0]; __syncthreads();
    float ex = (tid < PP) ? expf(v - mx) : 0.0f;
    red[tid] = ex; __syncthreads();
    for (int s = 128; s > 0; s >>= 1) { if (tid < s) red[tid] += red[tid+s]; __syncthreads(); }
    float inv = 1.0f / red[0];
    if (tid < PP) {
        float alpha = ex * inv;
        g_alpha[b*PP + tid] = alpha;
        float m = (g_declen[b] > t) ? 1.0f : 0.0f;
        out[OFF_ALPHA + ((size_t)b*TTT + t)*PP + tid] = alpha * m;
    }
}

// -------- staging --------
__global__ void k_stage(const float* __restrict__ enc, const float* __restrict__ emb,
                        const float* __restrict__ b_fbeta, int t) {
    __shared__ float al[PP];
    int b = blockIdx.y;
    int tid = threadIdx.x;
    for (int i = tid; i < PP; i += 128) al[i] = g_alpha[b*PP + i];
    __syncthreads();

    int j = blockIdx.x * 128 + tid;
    float outv;
    if (j < MMM) {
        int cap = g_caps[b*LLL + t];
        outv = emb[(size_t)cap * MMM + j];
    } else if (j < MMM + EE) {
        int jE = j - MMM;
        int sb = g_sortind[b];
        const float* eb = enc + (size_t)sb * PP * EE + jE;
        float awe0 = 0.f, awe1 = 0.f;
        #pragma unroll 8
        for (int p = 0; p < 192; p += 2) {
            awe0 = fmaf(al[p],     eb[(size_t)p * EE],       awe0);
            awe1 = fmaf(al[p + 1], eb[(size_t)(p + 1) * EE], awe1);
        }
        awe0 = fmaf(al[192], eb[(size_t)192 * EE], awe0);
        awe1 = fmaf(al[193], eb[(size_t)193 * EE], awe1);
        awe0 = fmaf(al[194], eb[(size_t)194 * EE], awe0);
        awe1 = fmaf(al[195], eb[(size_t)195 * EE], awe1);
        float awe = awe0 + awe1;
        float ga = b_fbeta[jE];
        #pragma unroll
        for (int s = 0; s < 8; ++s)
            ga += g_part2[((size_t)s * 32 + b) * NBIG + COL_GATE + jE];
        outv = awe * sigm(ga);
    } else {
        outv = g_h[b*DD + (j - (MMM + EE))];
    }
    g_x[b*KCC + j] = outv;
}

// -------- fin helper --------
__device__ __forceinline__ void fin_body(const float* __restrict__ b_fc,
                                         float* __restrict__ out, int t,
                                         int b, int j) {
    if (j >= VV) return;
    float v = 0.0f;
    if (g_declen[b] > t) {
        v = b_fc[j];
        #pragma unroll
        for (int s = 0; s < 4; ++s)
            v += g_part2[((size_t)s * 32 + b) * NBIG + COL_FC + j];
    }
    out[OFF_PRED + ((size_t)b*TTT + t)*VV + j] = v;
}

// -------- merged lstm(t) + fin(t-1) --------
__global__ void k_lstm_fin(const float* __restrict__ b_ih, const float* __restrict__ b_hh,
                           const float* __restrict__ b_fc, float* __restrict__ out, int t) {
    int bid = blockIdx.x;
    int tid = threadIdx.x;
    if (bid < 64) {
        int idx = bid * 256 + tid;
        int b = idx >> 9, d = idx & 511;
        float s[4];
        #pragma unroll
        for (int g = 0; g < 4; ++g) {
            float acc = b_ih[g*512 + d] + b_hh[g*512 + d];
            #pragma unroll
            for (int seg = 0; seg < 24; ++seg)
                acc += g_part[((size_t)seg * 32 + b) * G4 + g*512 + d];
            s[g] = acc;
        }
        float ig = sigm(s[0]), fg = sigm(s[1]), gg = tanhf(s[2]), og = sigm(s[3]);
        float cn = fg * g_c[idx] + ig * gg;
        float hn = og * tanhf(cn);
        if (g_declen[b] > t) { g_h[idx] = hn; g_c[idx] = cn; }
    } else {
        int tprev = t - 1;
        if (tprev < 0) return;
        int q = bid - 64;
        int b = q / 40;
        int j = (q % 40) * 256 + tid;
        fin_body(b_fc, out, tprev, b, j);
    }
}

__global__ void k_fin_tail(const float* __restrict__ b_fc, float* __restrict__ out) {
    int b = blockIdx.y;
    int j = blockIdx.x * 256 + threadIdx.x;
    fin_body(b_fc, out, TTT - 1, b, j);
}

// ============================================================================
extern "C" void kernel_launch(void* const* d_in, const int* in_sizes, int n_in,
                              void* d_out, int out_size) {
    const float* enc       = (const float*)d_in[0];
    const int*   caps_in   = (const int*)  d_in[1];
    const int*   lens      = (const int*)  d_in[2];
    const float* W_enc_att = (const float*)d_in[3];
    const float* b_enc_att = (const float*)d_in[4];
    const float* W_dec_att = (const float*)d_in[5];
    const float* b_dec_att = (const float*)d_in[6];
    const float* W_full    = (const float*)d_in[7];
    const float* b_full    = (const float*)d_in[8];
    const float* emb       = (const float*)d_in[9];
    const float* W_ih      = (const float*)d_in[10];
    const float* W_hh      = (const float*)d_in[11];
    const float* b_ih      = (const float*)d_in[12];
    const float* b_hh      = (const float*)d_in[13];
    const float* W_init_h  = (const float*)d_in[14];
    const float* b_init_h  = (const float*)d_in[15];
    const float* W_init_c  = (const float*)d_in[16];
    const float* b_init_c  = (const float*)d_in[17];
    const float* W_fbeta   = (const float*)d_in[18];
    const float* b_fbeta   = (const float*)d_in[19];
    const float* W_fc      = (const float*)d_in[20];
    const float* b_fc      = (const float*)d_in[21];
    float* out = (float*)d_out;

    k_setup<<<1, 32>>>(lens, caps_in, out);
    k_pack<<<57888, 256>>>(W_ih, W_hh, W_fc, W_fbeta, W_dec_att, W_init_h, W_init_c);
    k_mean<<<dim3(4, BB), 128>>>(enc);
    k_gemm_init<<<dim3(8, 16), 256>>>();
    k_init_fin<<<64, 256>>>(b_init_h, b_init_c);
    k_att1<<<dim3(49, 8), 128>>>(enc, W_enc_att, b_enc_att);
    k_gemm_small<<<dim3(20, 8), 256>>>();

    for (int t = 0; t < TTT; ++t) {
        k_attn<<<BB, 256>>>(b_dec_att, W_full, b_full, out, t);
        k_stage<<<dim3(24, BB), 128>>>(enc, emb, b_fbeta, t);
        k_gemm_gates_preds<<<700, 256>>>();
        k_lstm_fin<<<1344, 256>>>(b_ih, b_hh, b_fc, out, t);
        if (t < TTT - 1)
            k_gemm_small<<<dim3(20, 8), 256>>>();
    }
    k_gemm_preds<<<316, 256>>>();
    k_fin_tail<<<dim3(40, BB), 256>>>(b_fc, out);
    (void)in_sizes; (void)n_in; (void)out_size;
}